// round 11
// baseline (speedup 1.0000x reference)
#include <cuda_runtime.h>

// Problem constants (fixed by the reference):
//   N=100000 nodes, E=1600000 edges, IN=128, HID=64, OUT=8, B=16384
// NOTE: reference uses jnp.int64 but JAX x64 is disabled -> edge_index/idx are int32.
#define N_MAX 100000
#define E_MAX 1600000

// ---------------- scratch (device globals; no allocation allowed) ----------
__device__ __align__(256) int   g_deg[N_MAX];
__device__ __align__(256) int   g_rowstart[N_MAX + 1];
__device__ __align__(256) int   g_cursor[N_MAX];
__device__ __align__(256) int   g_srclist[E_MAX];
__device__ __align__(256) int   g_blocksums[512];
__device__ __align__(256) float g_y[(size_t)N_MAX * 128];  // [N][0:64)=x@W1_l, [64:128)=x@W1_r
__device__ __align__(256) float g_h[(size_t)N_MAX * 64];   // layer-1 activations
__device__ __align__(256) float g_z[(size_t)N_MAX * 8];    // h @ W2_l

// ---------------- stream/event for forked capture (created pre-main) --------
static cudaStream_t g_s2 = 0;
static cudaEvent_t  g_ev_fork = 0, g_ev_join = 0;
namespace {
struct StreamInit {
    StreamInit() {
        cudaStreamCreateWithFlags(&g_s2, cudaStreamNonBlocking);
        cudaEventCreateWithFlags(&g_ev_fork, cudaEventDisableTiming);
        cudaEventCreateWithFlags(&g_ev_join, cudaEventDisableTiming);
    }
};
static StreamInit g_stream_init;
}

// ---------------- packed f32x2 helpers (B300 double-rate fp32 path) ---------
__device__ __forceinline__ unsigned long long pk2(float lo, float hi) {
    unsigned long long r;
    asm("mov.b64 %0, {%1, %2};" : "=l"(r) : "f"(lo), "f"(hi));
    return r;
}
__device__ __forceinline__ unsigned long long fma2(unsigned long long a,
                                                   unsigned long long b,
                                                   unsigned long long c) {
    unsigned long long d;
    asm("fma.rn.f32x2 %0, %1, %2, %3;" : "=l"(d) : "l"(a), "l"(b), "l"(c));
    return d;
}
__device__ __forceinline__ float2 upk2(unsigned long long v) {
    float2 f;
    asm("mov.b64 {%0, %1}, %2;" : "=f"(f.x), "=f"(f.y) : "l"(v));
    return f;
}

// ---------------- CSR build --------------------------------------------------
__global__ void hist_kernel(const int* __restrict__ dst, int e) {
    int i = blockIdx.x * blockDim.x + threadIdx.x;
    if (i < e) atomicAdd(&g_deg[dst[i]], 1);
}

// per-block exclusive scan over 256 elements
__global__ void __launch_bounds__(256) scan_block_kernel(int n) {
    __shared__ int s[256];
    int i = blockIdx.x * 256 + threadIdx.x;
    int v = (i < n) ? g_deg[i] : 0;
    s[threadIdx.x] = v;
    __syncthreads();
#pragma unroll
    for (int off = 1; off < 256; off <<= 1) {
        int t = 0;
        if ((int)threadIdx.x >= off) t = s[threadIdx.x - off];
        __syncthreads();
        if ((int)threadIdx.x >= off) s[threadIdx.x] += t;
        __syncthreads();
    }
    if (i < n) g_rowstart[i] = s[threadIdx.x] - v;  // exclusive within block
    if (threadIdx.x == 255) g_blocksums[blockIdx.x] = s[255];
}

// add_offsets with inlined block-sum prefix: each block reduces
// g_blocksums[0..blockIdx) itself (<=391 values), then offsets its 256 rows.
__global__ void __launch_bounds__(256) add_offsets_kernel(int n, int e) {
    __shared__ int red[256];
    int b = blockIdx.x;
    int t = threadIdx.x;
    int part = 0;
    for (int i = t; i < b; i += 256) part += g_blocksums[i];
    red[t] = part;
    __syncthreads();
#pragma unroll
    for (int off = 128; off > 0; off >>= 1) {
        if (t < off) red[t] += red[t + off];
        __syncthreads();
    }
    int base = red[0];
    int i = b * 256 + t;
    if (i < n) {
        int r = g_rowstart[i] + base;
        g_rowstart[i] = r;
        g_cursor[i]   = r;
    }
    if (b == 0 && t == 0) g_rowstart[n] = e;
}

__global__ void scatter_kernel(const int* __restrict__ src,
                               const int* __restrict__ dst, int e) {
    int i = blockIdx.x * blockDim.x + threadIdx.x;
    if (i < e) {
        int d = dst[i];
        int p = atomicAdd(&g_cursor[d], 1);
        g_srclist[p] = src[i];
    }
}

// ---------------- GEMM1: y = x @ [W1_l | W1_r]  (N x 128 @ 128 x 128) -------
// Tile: BM=128, BN=128, BK=16; 256 threads, 8x8 register tile.
// Mainloop uses packed fma.rn.f32x2 (double-rate fp32); arithmetic bitwise
// identical to the scalar version (same fused ops, same accumulation order).
__global__ void __launch_bounds__(256) gemm1_kernel(const float* __restrict__ x,
                                                    const float* __restrict__ Wl,
                                                    const float* __restrict__ Wr,
                                                    int n) {
    __shared__ __align__(16) float xs[16][132];  // k-major, padded: 8448 B
    __shared__ __align__(16) float ws[16][128];  // 8192 B
    int tid = threadIdx.x;
    int row0 = blockIdx.x * 128;
    int tx = tid & 15;  // cols [tx*8, tx*8+8)
    int ty = tid >> 4;  // rows [ty*8, ty*8+8)

    unsigned long long acc2[8][4];  // [row][col-pair] packed f32x2
#pragma unroll
    for (int r = 0; r < 8; r++)
#pragma unroll
        for (int c = 0; c < 4; c++) acc2[r][c] = 0ull;

    int xr0 = tid >> 2;  // 0..63
    int xc4 = tid & 3;   // float4 slot within 16-wide k slab
    int wk0 = tid >> 5;  // 0..7
    int wc4 = tid & 31;  // 0..31 (c4<16 -> Wl, else Wr)

    for (int kb = 0; kb < 128; kb += 16) {
        // load x tile 128x16 -> xs[k][row] (transposed store)
#pragma unroll
        for (int it = 0; it < 2; it++) {
            int row = xr0 + it * 64;
            int gr = row0 + row;
            float4 v = make_float4(0.f, 0.f, 0.f, 0.f);
            if (gr < n) v = *(const float4*)(x + (size_t)gr * 128 + kb + xc4 * 4);
            xs[xc4 * 4 + 0][row] = v.x;
            xs[xc4 * 4 + 1][row] = v.y;
            xs[xc4 * 4 + 2][row] = v.z;
            xs[xc4 * 4 + 3][row] = v.w;
        }
        // load W tile 16x128 (cols 0:64 = Wl, 64:128 = Wr)
#pragma unroll
        for (int it = 0; it < 2; it++) {
            int k = wk0 + it * 8;
            float4 v;
            if (wc4 < 16) v = *(const float4*)(Wl + (kb + k) * 64 + wc4 * 4);
            else          v = *(const float4*)(Wr + (kb + k) * 64 + (wc4 - 16) * 4);
            *(float4*)&ws[k][wc4 * 4] = v;
        }
        __syncthreads();
#pragma unroll
        for (int k = 0; k < 16; k++) {
            float4 a0 = *(float4*)&xs[k][ty * 8];
            float4 a1 = *(float4*)&xs[k][ty * 8 + 4];
            float4 b0 = *(float4*)&ws[k][tx * 8];
            float4 b1 = *(float4*)&ws[k][tx * 8 + 4];
            unsigned long long bp[4] = {pk2(b0.x, b0.y), pk2(b0.z, b0.w),
                                        pk2(b1.x, b1.y), pk2(b1.z, b1.w)};
            float av[8] = {a0.x, a0.y, a0.z, a0.w, a1.x, a1.y, a1.z, a1.w};
#pragma unroll
            for (int r = 0; r < 8; r++) {
                unsigned long long ap = pk2(av[r], av[r]);
#pragma unroll
                for (int c = 0; c < 4; c++) acc2[r][c] = fma2(ap, bp[c], acc2[r][c]);
            }
        }
        __syncthreads();
    }
#pragma unroll
    for (int r = 0; r < 8; r++) {
        int gr = row0 + ty * 8 + r;
        if (gr < n) {
            float2 p0 = upk2(acc2[r][0]);
            float2 p1 = upk2(acc2[r][1]);
            float2 p2 = upk2(acc2[r][2]);
            float2 p3 = upk2(acc2[r][3]);
            *(float4*)(g_y + (size_t)gr * 128 + tx * 8) =
                make_float4(p0.x, p0.y, p1.x, p1.y);
            *(float4*)(g_y + (size_t)gr * 128 + tx * 8 + 4) =
                make_float4(p2.x, p2.y, p3.x, p3.y);
        }
    }
}

// ---------------- layer 1 combine + z -----------------------------------
// h = dropout(relu(agg/deg + y_r + b1)); z = h @ W2_l (warp butterfly reduce).
// 32 threads per node (float2 per thread), 8 nodes per 256-thread block.
__global__ void __launch_bounds__(256) layer1_kernel(const float* __restrict__ b1,
                                                     const float* __restrict__ mask,
                                                     const float* __restrict__ W2l,
                                                     int n) {
    __shared__ __align__(16) float w2[512];
    __shared__ float b1s[64];
    for (int i = threadIdx.x; i < 512; i += 256) w2[i] = W2l[i];
    if (threadIdx.x < 64) b1s[threadIdx.x] = b1[threadIdx.x];
    __syncthreads();

    int node = blockIdx.x * 8 + (threadIdx.x >> 5);
    int lane = threadIdx.x & 31;
    int d = lane * 2;
    if (node >= n) return;
    int s = g_rowstart[node];
    int epos = g_rowstart[node + 1];
    float2 a0 = make_float2(0.f, 0.f), a1 = make_float2(0.f, 0.f);
    float2 a2 = make_float2(0.f, 0.f), a3 = make_float2(0.f, 0.f);
    int e = s;
    for (; e + 4 <= epos; e += 4) {
        int s0 = g_srclist[e], s1 = g_srclist[e + 1];
        int s2 = g_srclist[e + 2], s3 = g_srclist[e + 3];
        float2 v0 = *(const float2*)(g_y + (size_t)s0 * 128 + d);
        float2 v1 = *(const float2*)(g_y + (size_t)s1 * 128 + d);
        float2 v2 = *(const float2*)(g_y + (size_t)s2 * 128 + d);
        float2 v3 = *(const float2*)(g_y + (size_t)s3 * 128 + d);
        a0.x += v0.x; a0.y += v0.y;
        a1.x += v1.x; a1.y += v1.y;
        a2.x += v2.x; a2.y += v2.y;
        a3.x += v3.x; a3.y += v3.y;
    }
    for (; e < epos; e++) {
        float2 v = *(const float2*)(g_y + (size_t)g_srclist[e] * 128 + d);
        a0.x += v.x; a0.y += v.y;
    }
    float sx = (a0.x + a1.x) + (a2.x + a3.x);
    float sy = (a0.y + a1.y) + (a2.y + a3.y);
    float inv = 1.0f / fmaxf((float)(epos - s), 1.0f);
    float2 yr = *(const float2*)(g_y + (size_t)node * 128 + 64 + d);
    float hx = sx * inv + yr.x + b1s[d];
    float hy = sy * inv + yr.y + b1s[d + 1];
    hx = fmaxf(hx, 0.0f);
    hy = fmaxf(hy, 0.0f);
    float2 mk = *(const float2*)(mask + (size_t)node * 64 + d);
    hx = (mk.x > 0.5f) ? hx * 2.0f : 0.0f;
    hy = (mk.y > 0.5f) ? hy * 2.0f : 0.0f;
    *(float2*)(g_h + (size_t)node * 64 + d) = make_float2(hx, hy);

    // z = h @ W2_l : per-lane partials over its 2 dims, butterfly across warp
    float zacc[8];
#pragma unroll
    for (int j = 0; j < 8; j++)
        zacc[j] = hx * w2[d * 8 + j] + hy * w2[(d + 1) * 8 + j];
#pragma unroll
    for (int off = 16; off > 0; off >>= 1)
#pragma unroll
        for (int j = 0; j < 8; j++)
            zacc[j] += __shfl_xor_sync(0xffffffffu, zacc[j], off);
    if (lane == 0) {
        float4* zp = (float4*)(g_z + (size_t)node * 8);
        zp[0] = make_float4(zacc[0], zacc[1], zacc[2], zacc[3]);
        zp[1] = make_float4(zacc[4], zacc[5], zacc[6], zacc[7]);
    }
}

// ---------------- output: out[b] = agg2(idx[b])/deg + h[idx[b]]@W2_r + b2 ---
__global__ void __launch_bounds__(256) out_kernel(const int* __restrict__ idx,
                                                  const float* __restrict__ W2r,
                                                  const float* __restrict__ b2,
                                                  float* __restrict__ out,
                                                  int bcnt) {
    __shared__ __align__(16) float w[512];
    __shared__ float bb[8];
    for (int i = threadIdx.x; i < 512; i += 256) w[i] = W2r[i];
    if (threadIdx.x < 8) bb[threadIdx.x] = b2[threadIdx.x];
    __syncthreads();
    int b = blockIdx.x * 32 + (threadIdx.x >> 3);
    int j = threadIdx.x & 7;
    if (b >= bcnt) return;
    int node = idx[b];
    int s = g_rowstart[node];
    int epos = g_rowstart[node + 1];
    float a0 = 0.f, a1 = 0.f, a2 = 0.f, a3 = 0.f;
    int e = s;
    for (; e + 4 <= epos; e += 4) {
        int s0 = g_srclist[e], s1 = g_srclist[e + 1];
        int s2 = g_srclist[e + 2], s3 = g_srclist[e + 3];
        a0 += g_z[(size_t)s0 * 8 + j];
        a1 += g_z[(size_t)s1 * 8 + j];
        a2 += g_z[(size_t)s2 * 8 + j];
        a3 += g_z[(size_t)s3 * 8 + j];
    }
    for (; e < epos; e++) a0 += g_z[(size_t)g_srclist[e] * 8 + j];
    float acc = ((a0 + a1) + (a2 + a3)) / fmaxf((float)(epos - s), 1.0f);
    const float* hr = g_h + (size_t)node * 64;
    float dot = 0.f;
#pragma unroll
    for (int k = 0; k < 64; k++) dot += hr[k] * w[k * 8 + j];
    out[(size_t)b * 8 + j] = acc + dot + bb[j];
}

// ---------------- launch -----------------------------------------------------
extern "C" void kernel_launch(void* const* d_in, const int* in_sizes, int n_in,
                              void* d_out, int out_size) {
    const float* x    = (const float*)d_in[0];
    const int*   edge = (const int*)d_in[1];   // int32 (JAX x64 disabled)
    const int*   idx  = (const int*)d_in[2];   // int32
    const float* mask = (const float*)d_in[3];
    const float* W1l  = (const float*)d_in[4];
    const float* W1r  = (const float*)d_in[5];
    const float* b1   = (const float*)d_in[6];
    const float* W2l  = (const float*)d_in[7];
    const float* W2r  = (const float*)d_in[8];
    const float* b2   = (const float*)d_in[9];
    float* out = (float*)d_out;

    int n = in_sizes[0] / 128;
    int e = in_sizes[1] / 2;
    int bcnt = in_sizes[2];
    const int* src = edge;
    const int* dst = edge + e;

    int nb = (n + 255) / 256;  // 391 blocks for N=100000

    void* deg_ptr = 0;
    cudaGetSymbolAddress(&deg_ptr, g_deg);

    // fork: CSR chain on side stream, concurrent with gemm1 on main stream
    cudaEventRecord(g_ev_fork, 0);
    cudaStreamWaitEvent(g_s2, g_ev_fork, 0);

    cudaMemsetAsync(deg_ptr, 0, n * sizeof(int), g_s2);
    hist_kernel<<<(e + 255) / 256, 256, 0, g_s2>>>(dst, e);
    scan_block_kernel<<<nb, 256, 0, g_s2>>>(n);
    add_offsets_kernel<<<nb, 256, 0, g_s2>>>(n, e);
    scatter_kernel<<<(e + 255) / 256, 256, 0, g_s2>>>(src, dst, e);
    cudaEventRecord(g_ev_join, g_s2);

    gemm1_kernel<<<(n + 127) / 128, 256>>>(x, W1l, W1r, n);

    // join: layer1 needs both CSR and gemm1
    cudaStreamWaitEvent(0, g_ev_join, 0);
    layer1_kernel<<<(n + 7) / 8, 256>>>(b1, mask, W2l, n);
    out_kernel<<<(bcnt + 31) / 32, 256>>>(idx, W2r, b2, out, bcnt);
}